// round 15
// baseline (speedup 1.0000x reference)
#include <cuda_runtime.h>
#include <cuda_bf16.h>
#include <cuda_fp16.h>
#include <math.h>
#include <stdint.h>

// Problem constants
#define BATCH 8
#define C 256
#define H 64
#define W 64
#define HW 4096
#define NPIX 32768
#define KK 9
#define CK 2304
#define CHW (C*HW)
#define PDIM 66
#define PP (PDIM*PDIM)

// ---------------- scratch (device globals; no allocation) ----------------
__device__ __half g_projh[(size_t)BATCH * CHW];          // proj in fp16 (16.8 MB)
__device__ float g_off[(size_t)BATCH * 27 * HW];
__device__ __half g_colh[(size_t)CK * NPIX];
__device__ __half g_wh[(size_t)C * CK];
__device__ __half g_xh[(size_t)BATCH * PP * 512];
__device__ __half g_owh[(size_t)9 * 32 * 512];
__device__ __half g_fh[(size_t)BATCH * CHW];
__device__ __half g_w1h[(size_t)C * C];
__device__ __half g_w1l[(size_t)C * C];
__device__ float g_inv1[C], g_add1[C], g_inv2[C], g_add2[C];

// ================= mma.sync / ldmatrix / cp.async helpers =================
__device__ __forceinline__ uint32_t smem_to_u32(const void* p) {
    uint32_t a;
    asm("{ .reg .u64 t; cvta.to.shared.u64 t, %1; cvt.u32.u64 %0, t; }" : "=r"(a) : "l"(p));
    return a;
}
__device__ __forceinline__ void cp16(uint32_t s, const void* g) {
    asm volatile("cp.async.cg.shared.global [%0], [%1], 16;" :: "r"(s), "l"(g));
}
#define CP_COMMIT() asm volatile("cp.async.commit_group;" ::: "memory")
#define CP_WAIT(n)  asm volatile("cp.async.wait_group %0;" :: "n"(n) : "memory")

__device__ __forceinline__ void ldsm4(uint32_t* r, uint32_t addr) {
    asm volatile("ldmatrix.sync.aligned.m8n8.x4.shared.b16 {%0,%1,%2,%3}, [%4];"
        : "=r"(r[0]), "=r"(r[1]), "=r"(r[2]), "=r"(r[3]) : "r"(addr));
}
__device__ __forceinline__ void ldsm4t(uint32_t* r, uint32_t addr) {
    asm volatile("ldmatrix.sync.aligned.m8n8.x4.trans.shared.b16 {%0,%1,%2,%3}, [%4];"
        : "=r"(r[0]), "=r"(r[1]), "=r"(r[2]), "=r"(r[3]) : "r"(addr));
}
__device__ __forceinline__ uint32_t lds32(uint32_t addr) {
    uint32_t v;
    asm volatile("ld.shared.b32 %0, [%1];" : "=r"(v) : "r"(addr));
    return v;
}
__device__ __forceinline__ void mma_fp(float* c, const uint32_t* a, const uint32_t* b) {
    asm volatile("mma.sync.aligned.m16n8k16.row.col.f32.f16.f16.f32 "
        "{%0,%1,%2,%3}, {%4,%5,%6,%7}, {%8,%9}, {%0,%1,%2,%3};"
        : "+f"(c[0]), "+f"(c[1]), "+f"(c[2]), "+f"(c[3])
        : "r"(a[0]), "r"(a[1]), "r"(a[2]), "r"(a[3]), "r"(b[0]), "r"(b[1]));
}

// ---------------- merged small prep (region-dispatched) --------------------
#define PS_SW1   1
#define PS_SW1E  (PS_SW1 + 2304)
#define PS_W1E   (PS_SW1E + 256)
#define PS_OWE   (PS_W1E + 576)
#define PS_TOTAL (PS_OWE + 4160)

__global__ void __launch_bounds__(256)
prep_small_kernel(const float* __restrict__ p1_w,  const float* __restrict__ p1_b,
                  const float* __restrict__ bn1_g, const float* __restrict__ bn1_b,
                  const float* __restrict__ bn1_m, const float* __restrict__ bn1_v,
                  const float* __restrict__ off_w,
                  const float* __restrict__ dcn_w, const float* __restrict__ dcn_b,
                  const float* __restrict__ bn2_g, const float* __restrict__ bn2_b,
                  const float* __restrict__ bn2_m, const float* __restrict__ bn2_v)
{
    const int bx = blockIdx.x;
    const int tid = threadIdx.x;

    if (bx == 0) {
        int o = tid;
        if (o < C) {
            float inv1 = bn1_g[o] * rsqrtf(bn1_v[o] + 1e-5f);
            g_inv1[o] = inv1;
            g_add1[o] = bn1_b[o] - bn1_m[o] * inv1 + p1_b[o] * inv1;
            float inv2 = bn2_g[o] * rsqrtf(bn2_v[o] + 1e-5f);
            g_inv2[o] = inv2;
            g_add2[o] = bn2_b[o] - bn2_m[o] * inv2 + dcn_b[o] * inv2;
        }
        return;
    }
    if (bx < PS_SW1E) {
        int idx = (bx - PS_SW1) * 256 + tid;
        if (idx < C * CK) {
            int o = idx / CK;
            float inv2 = bn2_g[o] * rsqrtf(bn2_v[o] + 1e-5f);
            g_wh[idx] = __float2half(dcn_w[idx] * inv2);
        }
        return;
    }
    if (bx < PS_W1E) {
        int idx = (bx - PS_SW1E) * 256 + tid;
        int o = idx >> 8;
        float inv1 = bn1_g[o] * rsqrtf(bn1_v[o] + 1e-5f);
        float v = p1_w[idx] * inv1;
        __half hi = __float2half(v);
        g_w1h[idx] = hi;
        g_w1l[idx] = __float2half(v - __half2float(hi));
        return;
    }
    if (bx < PS_OWE) {
        int idx = (bx - PS_W1E) * 256 + tid;
        int t = idx >> 14;
        int r = (idx >> 9) & 31;
        int c = idx & 511;
        float v = 0.0f;
        if (r < 27) {
            int kh = t / 3, kw = t % 3;
            v = off_w[((size_t)(r * 512 + c) * 3 + kh) * 3 + kw];
        }
        g_owh[idx] = __float2half(v);
        return;
    }
    {
        int idx = (bx - PS_OWE) * 256 + tid;
        if (idx < BATCH * 260 * 512) {
            int c = idx & 511;
            int rest = idx >> 9;
            int pos = rest % 260;
            int b = rest / 260;
            int yp, xp;
            if (pos < 66)       { yp = 0;  xp = pos; }
            else if (pos < 132) { yp = 65; xp = pos - 66; }
            else {
                int i = pos - 132;
                yp = 1 + (i >> 1);
                xp = (i & 1) * 65;
            }
            size_t a = ((size_t)b * PP + yp * PDIM + xp) * 512 + c;
            g_xh[a] = __float2half(0.0f);
        }
    }
}

// feature -> fp16 (single)
__global__ void conv_f16_kernel(const float* __restrict__ feature)
{
    size_t idx = (size_t)blockIdx.x * 256 + threadIdx.x;
    if (idx < (size_t)BATCH * CHW) {
        g_fh[idx] = __float2half(feature[idx]);
    }
}

// pack concat(flip(g_fh), g_projh) transposed -> X^T[b][pad pos][512] fp16
__global__ void __launch_bounds__(256)
pack_kernel()
{
    __shared__ __half tile[32][34];
    const int tx = threadIdx.x, ty = threadIdx.y;
    const int b = blockIdx.z >> 6;
    const int y = blockIdx.z & 63;
    const int x0 = blockIdx.x * 32;
    const int c0 = blockIdx.y * 32;

#pragma unroll
    for (int j = 0; j < 4; j++) {
        int c = c0 + ty + j * 8;
        int x = x0 + tx;
        __half v;
        if (c < 256) v = g_fh[((size_t)(b * 256 + c) * 64 + y) * 64 + (63 - x)];
        else         v = g_projh[((size_t)(b * 256 + (c - 256)) * 64 + y) * 64 + x];
        tile[ty + j * 8][tx] = v;
    }
    __syncthreads();
#pragma unroll
    for (int j = 0; j < 4; j++) {
        int xl = ty + j * 8;
        __half v = tile[tx][xl];
        size_t a = ((size_t)b * PP + (y + 1) * PDIM + (x0 + xl + 1)) * 512 + c0 + tx;
        g_xh[a] = v;
    }
}

// ---------------- proj GEMM: mma.sync fp16 2-term (Wh+Wl)·Fh ---------------
#define PJ_NCH 8
#define PJ_ASTR 40
#define PJ_BSTR 136
#define PJ_A_BYTES (128 * PJ_ASTR * 2)
#define PJ_B_BYTES (32 * PJ_BSTR * 2)
#define PJ_STAGE (2 * PJ_A_BYTES + PJ_B_BYTES)
#define PJ_SMEM (2 * PJ_STAGE)

__global__ void __launch_bounds__(256, 1)
proj_tc_kernel()
{
    extern __shared__ char smem[];
    const uint32_t sbase = smem_to_u32(smem);
    const int tid = threadIdx.x;
    const int lane = tid & 31;
    const int wid = tid >> 5;

    const int n0 = blockIdx.x * 128;
    const int m0 = blockIdx.y * 128;
    const int bb = n0 >> 12;
    const int hw0 = n0 & 4095;
    const int wm = (wid >> 2) * 64;
    const int wn = (wid & 3) * 32;

    const __half* wh = g_w1h + (size_t)m0 * C;
    const __half* wl = g_w1l + (size_t)m0 * C;
    const __half* fh = g_fh + (size_t)bb * CHW + hw0;

    float acc[4][4][4];
#pragma unroll
    for (int i = 0; i < 4; i++)
#pragma unroll
        for (int j = 0; j < 4; j++)
#pragma unroll
            for (int t = 0; t < 4; t++) acc[i][j][t] = 0.0f;

    auto load_chunk = [&](int st, int kt) {
        const uint32_t s = sbase + st * PJ_STAGE;
        const int k0 = kt * 32;
#pragma unroll
        for (int i = 0; i < 2; i++) {
            int idx = i * 256 + tid;
            int r = idx >> 2, kseg = idx & 3;
            size_t go = (size_t)r * C + k0 + kseg * 8;
            uint32_t so = (uint32_t)(r * PJ_ASTR + kseg * 8) * 2;
            cp16(s + so, wh + go);
            cp16(s + PJ_A_BYTES + so, wl + go);
        }
#pragma unroll
        for (int i = 0; i < 2; i++) {
            int idx = i * 256 + tid;
            int kr = idx >> 4, nseg = idx & 15;
            size_t go = (size_t)(k0 + kr) * HW + nseg * 8;
            uint32_t so = (uint32_t)(kr * PJ_BSTR + nseg * 8) * 2;
            cp16(s + 2 * PJ_A_BYTES + so, fh + go);
        }
        CP_COMMIT();
    };

    load_chunk(0, 0);

    for (int kt = 0; kt < PJ_NCH; kt++) {
        const int st = kt & 1;
        if (kt + 1 < PJ_NCH) { load_chunk(st ^ 1, kt + 1); CP_WAIT(1); }
        else                 { CP_WAIT(0); }
        __syncthreads();

        const uint32_t sAh = sbase + st * PJ_STAGE;
        const uint32_t sAl = sAh + PJ_A_BYTES;
        const uint32_t sBh = sAh + 2 * PJ_A_BYTES;

#pragma unroll
        for (int ks = 0; ks < 2; ks++) {
            uint32_t ah[4][4], al[4][4], bh[4][2];

            const int arow = wm + (lane & 15);
            const int acol = ks * 16 + ((lane >> 4) << 3);
#pragma unroll
            for (int tm = 0; tm < 4; tm++) {
                uint32_t ao = (uint32_t)((arow + tm * 16) * PJ_ASTR + acol) * 2;
                ldsm4(ah[tm], sAh + ao);
                ldsm4(al[tm], sAl + ao);
            }
            const int bkrow = ks * 16 + (lane & 15);
#pragma unroll
            for (int ng = 0; ng < 2; ng++) {
                const int bcol = wn + ng * 16 + ((lane >> 4) << 3);
                uint32_t bo = (uint32_t)(bkrow * PJ_BSTR + bcol) * 2;
                uint32_t t[4];
                ldsm4t(t, sBh + bo);
                bh[2*ng][0] = t[0]; bh[2*ng][1] = t[1];
                bh[2*ng+1][0] = t[2]; bh[2*ng+1][1] = t[3];
            }
#pragma unroll
            for (int tm = 0; tm < 4; tm++)
#pragma unroll
                for (int tn = 0; tn < 4; tn++) {
                    mma_fp(acc[tm][tn], ah[tm], bh[tn]);
                    mma_fp(acc[tm][tn], al[tm], bh[tn]);
                }
        }
        __syncthreads();
    }

    const int rowl = lane >> 2;
    const int colp = (lane & 3) * 2;
#pragma unroll
    for (int tm = 0; tm < 4; tm++) {
#pragma unroll
        for (int half = 0; half < 2; half++) {
            const int m = m0 + wm + tm * 16 + rowl + half * 8;
            const float add = g_add1[m];
            __half* ob = g_projh + ((size_t)bb * C + m) * HW + hw0 + wn + colp;
#pragma unroll
            for (int tn = 0; tn < 4; tn++) {
                float2 r;
                r.x = acc[tm][tn][half * 2 + 0] + add;
                r.y = acc[tm][tn][half * 2 + 1] + add;
                *(__half2*)(ob + tn * 8) = __float22half2_rn(r);
            }
        }
    }
}

// ---------------- offset conv as tensor-core GEMM (fp16 single, 3-stage) ---
#define OC_ROWS 396
#define OC_BSTR 40
#define OC_ASTR 40
#define OC_B_BYTES (OC_ROWS * OC_BSTR * 2)
#define OC_A_BYTES (9 * 32 * OC_ASTR * 2)
#define OC_STAGE (OC_B_BYTES + OC_A_BYTES)
#define OC_SMEM (3 * OC_STAGE)

__global__ void __launch_bounds__(256, 1)
off_gemm_kernel(const float* __restrict__ off_b)
{
    extern __shared__ char smem[];
    const uint32_t sbase = smem_to_u32(smem);
    const int tid = threadIdx.x;
    const int lane = tid & 31;
    const int wid = tid >> 5;

    const int n0 = blockIdx.x * 256;
    const int bb = n0 >> 12;
    const int hw0 = n0 & 4095;
    const int h0 = hw0 >> 6;

    const int wm = (wid >> 2) * 16;
    const int wn = (wid & 3) * 64;

    const size_t pbase = (size_t)bb * PP + h0 * PDIM;

    uint32_t rowb[8];
#pragma unroll
    for (int nt = 0; nt < 8; nt++) {
        int nl = wn + nt * 8 + (lane >> 2);
        int row = ((nl >> 6) + 1) * PDIM + (nl & 63) + 1;
        rowb[nt] = (uint32_t)(row * OC_BSTR + (lane & 3) * 2) * 2;
    }
    const int am = wm + (lane & 15);
    const int acol2 = (lane >> 4) << 3;

    float acc[8][4];
#pragma unroll
    for (int i = 0; i < 8; i++)
#pragma unroll
        for (int j = 0; j < 4; j++) acc[i][j] = 0.0f;

    auto load_chunk = [&](int st, int kc) {
        const uint32_t s = sbase + st * OC_STAGE;
        const int k0 = kc * 32;
#pragma unroll
        for (int i = 0; i < 7; i++) {
            int idx = i * 256 + tid;
            if (idx < 1584) {
                int r = idx >> 2, c4 = idx & 3;
                size_t go = (pbase + r) * 512 + k0 + c4 * 8;
                uint32_t so = (uint32_t)(r * OC_BSTR + c4 * 8) * 2;
                cp16(s + so, g_xh + go);
            }
        }
#pragma unroll
        for (int i = 0; i < 5; i++) {
            int idx = i * 256 + tid;
            if (idx < 1152) {
                int r = idx >> 2, c4 = idx & 3;
                size_t go = (size_t)r * 512 + k0 + c4 * 8;
                uint32_t so = (uint32_t)(r * OC_ASTR + c4 * 8) * 2;
                cp16(s + OC_B_BYTES + so, g_owh + go);
            }
        }
        CP_COMMIT();
    };

    const int stapB[9] = {(-PDIM-1)*OC_BSTR*2, (-PDIM)*OC_BSTR*2, (-PDIM+1)*OC_BSTR*2,
                          (-1)*OC_BSTR*2, 0, (1)*OC_BSTR*2,
                          (PDIM-1)*OC_BSTR*2, (PDIM)*OC_BSTR*2, (PDIM+1)*OC_BSTR*2};

    load_chunk(0, 0);
    load_chunk(1, 1);

    int st = 0;
    for (int kc = 0; kc < 16; kc++) {
        if (kc + 2 < 16) load_chunk((st + 2) % 3, kc + 2);
        else             CP_COMMIT();
        CP_WAIT(2);
        __syncthreads();

        const uint32_t sB  = sbase + st * OC_STAGE;
        const uint32_t sAh = sB + OC_B_BYTES;

#pragma unroll
        for (int tap = 0; tap < 9; tap++) {
            const int sb_t = stapB[tap];
#pragma unroll
            for (int ks = 0; ks < 2; ks++) {
                uint32_t ah[4];
                uint32_t ao = (uint32_t)((tap * 32 + am) * OC_ASTR + ks * 16 + acol2) * 2;
                ldsm4(ah, sAh + ao);
#pragma unroll
                for (int nt = 0; nt < 8; nt++) {
                    uint32_t base = sB + rowb[nt] + sb_t + ks * 32;
                    uint32_t b[2];
                    b[0] = lds32(base);
                    b[1] = lds32(base + 16);
                    mma_fp(acc[nt], ah, b);
                }
            }
        }
        __syncthreads();
        st = (st + 1) % 3;
    }

    const int mr = wm + (lane >> 2);
    const int cb = hw0 + wn + (lane & 3) * 2;
#pragma unroll
    for (int half = 0; half < 2; half++) {
        int m = mr + half * 8;
        if (m < 27) {
            float bias = off_b[m];
            float* ob = g_off + ((size_t)(bb * 27 + m)) * HW + cb;
#pragma unroll
            for (int nt = 0; nt < 8; nt++) {
                float2 r;
                r.x = acc[nt][half * 2 + 0] + bias;
                r.y = acc[nt][half * 2 + 1] + bias;
                *(float2*)(ob + nt * 8) = r;
            }
        }
    }
}

// ---------------- sampling v2: channel-contiguous gathers from g_xh --------
#define SP_PITCH 258

__global__ void __launch_bounds__(256)
sample_v2_kernel()
{
    __shared__ __half tile[64 * SP_PITCH];
    __shared__ float s_w[4][64];
    __shared__ int   s_a[4][64];

    const int tid = threadIdx.x;
    const int h = blockIdx.x;
    const int k = blockIdx.y;
    const int b = blockIdx.z;

    if (tid < 64) {
        const int w = tid;
        const int hw = h * W + w;
        const size_t obase = (size_t)(b * 27) * HW + hw;
        const float dy = g_off[obase + (size_t)k * HW];
        const float dx = g_off[obase + (size_t)(9 + k) * HW];
        const float mr = g_off[obase + (size_t)(18 + k) * HW];
        const float m  = 1.0f / (1.0f + expf(-mr));

        const int ky = k / 3 - 1, kx = k % 3 - 1;
        const float py = (float)(h + ky) + dy;
        const float px = (float)(w + kx) + dx;

        const float y0f = floorf(py), x0f = floorf(px);
        const float wy = py - y0f, wx = px - x0f;
        const int y0 = (int)y0f, x0 = (int)x0f;
        const int y1 = y0 + 1,   x1 = x0 + 1;

        const bool vy0 = (y0 >= 0) && (y0 < H);
        const bool vy1 = (y1 >= 0) && (y1 < H);
        const bool vx0 = (x0 >= 0) && (x0 < W);
        const bool vx1 = (x1 >= 0) && (x1 < W);

        s_w[0][w] = (1.0f - wy) * (1.0f - wx) * ((vy0 && vx0) ? m : 0.0f);
        s_w[1][w] = (1.0f - wy) * wx          * ((vy0 && vx1) ? m : 0.0f);
        s_w[2][w] = wy * (1.0f - wx)          * ((vy1 && vx0) ? m : 0.0f);
        s_w[3][w] = wy * wx                   * ((vy1 && vx1) ? m : 0.0f);

        const int yc0 = min(max(y0, 0), H - 1);
        const int yc1 = min(max(y1, 0), H - 1);
        const int xc0 = min(max(x0, 0), W - 1);
        const int xc1 = min(max(x1, 0), W - 1);

        s_a[0][w] = (yc0 + 1) * PDIM + xc0 + 1;
        s_a[1][w] = (yc0 + 1) * PDIM + xc1 + 1;
        s_a[2][w] = (yc1 + 1) * PDIM + xc0 + 1;
        s_a[3][w] = (yc1 + 1) * PDIM + xc1 + 1;
    }
    __syncthreads();

    const __half* xb = g_xh + (size_t)b * PP * 512;
    const int cpair = tid & 127;
    const int pxg = tid >> 7;

    for (int px = pxg; px < 64; px += 2) {
        const float w00 = s_w[0][px], w01 = s_w[1][px];
        const float w10 = s_w[2][px], w11 = s_w[3][px];
        const __half2 f00 = *((const __half2*)(xb + (size_t)s_a[0][px] * 512) + cpair);
        const __half2 f01 = *((const __half2*)(xb + (size_t)s_a[1][px] * 512) + cpair);
        const __half2 f10 = *((const __half2*)(xb + (size_t)s_a[2][px] * 512) + cpair);
        const __half2 f11 = *((const __half2*)(xb + (size_t)s_a[3][px] * 512) + cpair);
        float2 a = __half22float2(f00), bq = __half22float2(f01);
        float2 c2 = __half22float2(f10), d = __half22float2(f11);
        float2 r;
        r.x = w00 * a.x + w01 * bq.x + w10 * c2.x + w11 * d.x;
        r.y = w00 * a.y + w01 * bq.y + w10 * c2.y + w11 * d.y;
        *(__half2*)&tile[px * SP_PITCH + 2 * cpair] = __float22half2_rn(r);
    }
    __syncthreads();

    const int lane = tid & 31, wid = tid >> 5;
    const size_t outb = (size_t)b * HW + h * 64 + 2 * lane;
#pragma unroll 4
    for (int i = 0; i < 32; i++) {
        const int c = wid * 32 + i;
        __half v0 = tile[(2 * lane)     * SP_PITCH + c];
        __half v1 = tile[(2 * lane + 1) * SP_PITCH + c];
        *(__half2*)(g_colh + ((size_t)c * KK + k) * NPIX + outb) = __halves2half2(v0, v1);
    }
}

// ---------------- DCN GEMM: mma.sync fp16 single-term, 3-stage, M=128 ------
#define DCN_NCH 72
#define A_STRIDE 40
#define B_STRIDE 136
#define A_BYTES (128 * A_STRIDE * 2)
#define B_BYTES (32 * B_STRIDE * 2)
#define STAGE_BYTES (A_BYTES + B_BYTES)
#define DCN_SMEM (3 * STAGE_BYTES)

__global__ void __launch_bounds__(256, 1)
dcn_gemm_kernel(float* __restrict__ out)
{
    extern __shared__ char smem[];
    const uint32_t sbase = smem_to_u32(smem);
    const int tid = threadIdx.x;
    const int lane = tid & 31;
    const int wid = tid >> 5;

    const int n0 = blockIdx.x * 128;
    const int m0 = blockIdx.y * 128;
    const int bb = n0 >> 12;
    const int hw0 = n0 & 4095;
    const int wm = (wid >> 2) * 64;
    const int wn = (wid & 3) * 32;

    const __half* wh = g_wh + (size_t)m0 * CK;

    float acc[4][4][4];
#pragma unroll
    for (int i = 0; i < 4; i++)
#pragma unroll
        for (int j = 0; j < 4; j++)
#pragma unroll
            for (int t = 0; t < 4; t++) acc[i][j][t] = 0.0f;

    auto load_chunk = [&](int st, int kt) {
        const uint32_t s = sbase + st * STAGE_BYTES;
        const int k0 = kt * 32;
#pragma unroll
        for (int i = 0; i < 2; i++) {
            int idx = i * 256 + tid;
            int r = idx >> 2, kseg = idx & 3;
            size_t go = (size_t)r * CK + k0 + kseg * 8;
            uint32_t so = (uint32_t)(r * A_STRIDE + kseg * 8) * 2;
            cp16(s + so, wh + go);
        }
#pragma unroll
        for (int i = 0; i < 2; i++) {
            int idx = i * 256 + tid;
            int kr = idx >> 4, nseg = idx & 15;
            size_t go = (size_t)(k0 + kr) * NPIX + n0 + nseg * 8;
            uint32_t so = (uint32_t)(kr * B_STRIDE + nseg * 8) * 2;
            cp16(s + A_BYTES + so, g_colh + go);
        }
        CP_COMMIT();
    };

    load_chunk(0, 0);
    load_chunk(1, 1);

    int st = 0;
    for (int kt = 0; kt < DCN_NCH; kt++) {
        if (kt + 2 < DCN_NCH) load_chunk((st + 2) % 3, kt + 2);
        else                  CP_COMMIT();
        CP_WAIT(2);
        __syncthreads();

        const uint32_t sA = sbase + st * STAGE_BYTES;
        const uint32_t sB = sA + A_BYTES;

#pragma unroll
        for (int ks = 0; ks < 2; ks++) {
            uint32_t ah[4][4], bf[4][2];

            const int arow = wm + (lane & 15);
            const int acol = ks * 16 + ((lane >> 4) << 3);
#pragma unroll
            for (int tm = 0; tm < 4; tm++) {
                uint32_t ao = (uint32_t)((arow + tm * 16) * A_STRIDE + acol) * 2;
                ldsm4(ah[tm], sA + ao);
            }
            const int bkrow = ks * 16 + (lane & 15);
#pragma unroll
            for (int ng = 0; ng < 2; ng++) {
                const int bcol = wn + ng * 16 + ((lane >> 4) << 3);
                uint32_t bo = (uint32_t)(bkrow * B_STRIDE + bcol) * 2;
                uint32_t t[4];
                ldsm4t(t, sB + bo);
                bf[2*ng][0] = t[0]; bf[2*ng][1] = t[1];
                bf[2*ng+1][0] = t[2]; bf[2*ng+1][1] = t[3];
            }
#pragma unroll
            for (int tm = 0; tm < 4; tm++)
#pragma unroll
                for (int tn = 0; tn < 4; tn++)
                    mma_fp(acc[tm][tn], ah[tm], bf[tn]);
        }
        __syncthreads();
        st = (st + 1) % 3;
    }

    const int rowl = lane >> 2;
    const int colp = (lane & 3) * 2;
#pragma unroll
    for (int tm = 0; tm < 4; tm++) {
#pragma unroll
        for (int half = 0; half < 2; half++) {
            const int m = m0 + wm + tm * 16 + rowl + half * 8;
            const float add = g_add2[m];
            const __half* pr = g_projh + ((size_t)bb * C + m) * HW + hw0 + wn + colp;
            float*        ob = out     + ((size_t)bb * C + m) * HW + hw0 + wn + colp;
#pragma unroll
            for (int tn = 0; tn < 4; tn++) {
                float2 p = __half22float2(*(const __half2*)(pr + tn * 8));
                float2 r;
                r.x = fmaxf(acc[tm][tn][half * 2 + 0] + add + p.x, 0.0f);
                r.y = fmaxf(acc[tm][tn][half * 2 + 1] + add + p.y, 0.0f);
                *(float2*)(ob + tn * 8) = r;
            }
        }
    }
}

// ---------------- launch ----------------------------------------------------
extern "C" void kernel_launch(void* const* d_in, const int* in_sizes, int n_in,
                              void* d_out, int out_size)
{
    const float* feature = (const float*)d_in[0];
    const float* p1_w    = (const float*)d_in[1];
    const float* p1_b    = (const float*)d_in[2];
    const float* bn1_g   = (const float*)d_in[3];
    const float* bn1_b   = (const float*)d_in[4];
    const float* bn1_m   = (const float*)d_in[5];
    const float* bn1_v   = (const float*)d_in[6];
    const float* off_w   = (const float*)d_in[7];
    const float* off_b   = (const float*)d_in[8];
    const float* dcn_w   = (const float*)d_in[9];
    const float* dcn_b   = (const float*)d_in[10];
    const float* bn2_g   = (const float*)d_in[11];
    const float* bn2_b   = (const float*)d_in[12];
    const float* bn2_m   = (const float*)d_in[13];
    const float* bn2_v   = (const float*)d_in[14];

    cudaFuncSetAttribute(dcn_gemm_kernel,
                         cudaFuncAttributeMaxDynamicSharedMemorySize, DCN_SMEM);
    cudaFuncSetAttribute(off_gemm_kernel,
                         cudaFuncAttributeMaxDynamicSharedMemorySize, OC_SMEM);
    cudaFuncSetAttribute(proj_tc_kernel,
                         cudaFuncAttributeMaxDynamicSharedMemorySize, PJ_SMEM);

    prep_small_kernel<<<PS_TOTAL, 256>>>(p1_w, p1_b, bn1_g, bn1_b, bn1_m, bn1_v,
                                         off_w, dcn_w, dcn_b,
                                         bn2_g, bn2_b, bn2_m, bn2_v);
    conv_f16_kernel<<<(int)(((size_t)BATCH * CHW + 255) / 256), 256>>>(feature);

    proj_tc_kernel<<<dim3(NPIX / 128, 2), 256, PJ_SMEM>>>();

    pack_kernel<<<dim3(2, 16, 512), dim3(32, 8)>>>();

    off_gemm_kernel<<<NPIX / 256, 256, OC_SMEM>>>(off_b);

    sample_v2_kernel<<<dim3(H, KK, BATCH), 256>>>();

    dcn_gemm_kernel<<<dim3(NPIX / 128, C / 128), 256, DCN_SMEM>>>((float*)d_out);
}

// round 16
// speedup vs baseline: 1.0413x; 1.0413x over previous
#include <cuda_runtime.h>
#include <cuda_bf16.h>
#include <cuda_fp16.h>
#include <math.h>
#include <stdint.h>

// Problem constants
#define BATCH 8
#define C 256
#define H 64
#define W 64
#define HW 4096
#define NPIX 32768
#define KK 9
#define CK 2304
#define CHW (C*HW)
#define PDIM 66
#define PP (PDIM*PDIM)

// ---------------- scratch (device globals; no allocation) ----------------
__device__ __half g_projh[(size_t)BATCH * CHW];          // proj in fp16
__device__ float g_off[(size_t)BATCH * 27 * HW];
__device__ __half g_colh[(size_t)CK * NPIX];
__device__ __half g_wh[(size_t)C * CK];
__device__ __half g_xh[(size_t)BATCH * PP * 512];
__device__ __half g_owh[(size_t)9 * 32 * 512];
__device__ __half g_fh[(size_t)BATCH * CHW];
__device__ __half g_w1h[(size_t)C * C];
__device__ __half g_w1l[(size_t)C * C];
__device__ float g_inv1[C], g_add1[C], g_inv2[C], g_add2[C];

// ================= mma.sync / ldmatrix / cp.async helpers =================
__device__ __forceinline__ uint32_t smem_to_u32(const void* p) {
    uint32_t a;
    asm("{ .reg .u64 t; cvta.to.shared.u64 t, %1; cvt.u32.u64 %0, t; }" : "=r"(a) : "l"(p));
    return a;
}
__device__ __forceinline__ void cp16(uint32_t s, const void* g) {
    asm volatile("cp.async.cg.shared.global [%0], [%1], 16;" :: "r"(s), "l"(g));
}
#define CP_COMMIT() asm volatile("cp.async.commit_group;" ::: "memory")
#define CP_WAIT(n)  asm volatile("cp.async.wait_group %0;" :: "n"(n) : "memory")

__device__ __forceinline__ void ldsm4(uint32_t* r, uint32_t addr) {
    asm volatile("ldmatrix.sync.aligned.m8n8.x4.shared.b16 {%0,%1,%2,%3}, [%4];"
        : "=r"(r[0]), "=r"(r[1]), "=r"(r[2]), "=r"(r[3]) : "r"(addr));
}
__device__ __forceinline__ void ldsm4t(uint32_t* r, uint32_t addr) {
    asm volatile("ldmatrix.sync.aligned.m8n8.x4.trans.shared.b16 {%0,%1,%2,%3}, [%4];"
        : "=r"(r[0]), "=r"(r[1]), "=r"(r[2]), "=r"(r[3]) : "r"(addr));
}
__device__ __forceinline__ uint32_t lds32(uint32_t addr) {
    uint32_t v;
    asm volatile("ld.shared.b32 %0, [%1];" : "=r"(v) : "r"(addr));
    return v;
}
__device__ __forceinline__ void mma_fp(float* c, const uint32_t* a, const uint32_t* b) {
    asm volatile("mma.sync.aligned.m16n8k16.row.col.f32.f16.f16.f32 "
        "{%0,%1,%2,%3}, {%4,%5,%6,%7}, {%8,%9}, {%0,%1,%2,%3};"
        : "+f"(c[0]), "+f"(c[1]), "+f"(c[2]), "+f"(c[3])
        : "r"(a[0]), "r"(a[1]), "r"(a[2]), "r"(a[3]), "r"(b[0]), "r"(b[1]));
}

// ---------------- merged small prep (region-dispatched) --------------------
#define PS_SW1   1
#define PS_SW1E  (PS_SW1 + 2304)
#define PS_W1E   (PS_SW1E + 256)
#define PS_OWE   (PS_W1E + 576)
#define PS_TOTAL (PS_OWE + 4160)

__global__ void __launch_bounds__(256)
prep_small_kernel(const float* __restrict__ p1_w,  const float* __restrict__ p1_b,
                  const float* __restrict__ bn1_g, const float* __restrict__ bn1_b,
                  const float* __restrict__ bn1_m, const float* __restrict__ bn1_v,
                  const float* __restrict__ off_w,
                  const float* __restrict__ dcn_w, const float* __restrict__ dcn_b,
                  const float* __restrict__ bn2_g, const float* __restrict__ bn2_b,
                  const float* __restrict__ bn2_m, const float* __restrict__ bn2_v)
{
    const int bx = blockIdx.x;
    const int tid = threadIdx.x;

    if (bx == 0) {
        int o = tid;
        if (o < C) {
            float inv1 = bn1_g[o] * rsqrtf(bn1_v[o] + 1e-5f);
            g_inv1[o] = inv1;
            g_add1[o] = bn1_b[o] - bn1_m[o] * inv1 + p1_b[o] * inv1;
            float inv2 = bn2_g[o] * rsqrtf(bn2_v[o] + 1e-5f);
            g_inv2[o] = inv2;
            g_add2[o] = bn2_b[o] - bn2_m[o] * inv2 + dcn_b[o] * inv2;
        }
        return;
    }
    if (bx < PS_SW1E) {
        int idx = (bx - PS_SW1) * 256 + tid;
        if (idx < C * CK) {
            int o = idx / CK;
            float inv2 = bn2_g[o] * rsqrtf(bn2_v[o] + 1e-5f);
            g_wh[idx] = __float2half(dcn_w[idx] * inv2);
        }
        return;
    }
    if (bx < PS_W1E) {
        int idx = (bx - PS_SW1E) * 256 + tid;
        int o = idx >> 8;
        float inv1 = bn1_g[o] * rsqrtf(bn1_v[o] + 1e-5f);
        float v = p1_w[idx] * inv1;
        __half hi = __float2half(v);
        g_w1h[idx] = hi;
        g_w1l[idx] = __float2half(v - __half2float(hi));
        return;
    }
    if (bx < PS_OWE) {
        int idx = (bx - PS_W1E) * 256 + tid;
        int t = idx >> 14;
        int r = (idx >> 9) & 31;
        int c = idx & 511;
        float v = 0.0f;
        if (r < 27) {
            int kh = t / 3, kw = t % 3;
            v = off_w[((size_t)(r * 512 + c) * 3 + kh) * 3 + kw];
        }
        g_owh[idx] = __float2half(v);
        return;
    }
    {
        int idx = (bx - PS_OWE) * 256 + tid;
        if (idx < BATCH * 260 * 512) {
            int c = idx & 511;
            int rest = idx >> 9;
            int pos = rest % 260;
            int b = rest / 260;
            int yp, xp;
            if (pos < 66)       { yp = 0;  xp = pos; }
            else if (pos < 132) { yp = 65; xp = pos - 66; }
            else {
                int i = pos - 132;
                yp = 1 + (i >> 1);
                xp = (i & 1) * 65;
            }
            size_t a = ((size_t)b * PP + yp * PDIM + xp) * 512 + c;
            g_xh[a] = __float2half(0.0f);
        }
    }
}

// feature -> fp16, vectorized x8 (2x LDG.128, 1x STG.128 per thread)
__global__ void conv_f16_kernel(const float* __restrict__ feature)
{
    size_t i8 = ((size_t)blockIdx.x * 256 + threadIdx.x) * 8;
    float4 a = *(const float4*)(feature + i8);
    float4 b = *(const float4*)(feature + i8 + 4);
    __half2 h[4];
    h[0] = __floats2half2_rn(a.x, a.y);
    h[1] = __floats2half2_rn(a.z, a.w);
    h[2] = __floats2half2_rn(b.x, b.y);
    h[3] = __floats2half2_rn(b.z, b.w);
    *(uint4*)(g_fh + i8) = *(uint4*)h;
}

// pack v2: half2 everywhere; concat(flip(g_fh), g_projh) -> X^T fp16
__global__ void __launch_bounds__(256)
pack_kernel()
{
    __shared__ __half tile[32][36];
    const int tid = threadIdx.x;
    const int b = blockIdx.z >> 6;
    const int y = blockIdx.z & 63;
    const int x0 = blockIdx.x * 32;
    const int c0 = blockIdx.y * 32;

    // load: each thread 2 iterations of one half2 (2 x-positions, 1 channel)
    {
        const int txp = tid & 15;          // x-pair index
        const int crow = tid >> 4;         // 0..15
#pragma unroll
        for (int j = 0; j < 2; j++) {
            int cl = crow + j * 16;        // 0..31
            int c = c0 + cl;
            __half2 v;
            if (c < 256) {
                const __half* base = g_fh + ((size_t)(b * 256 + c) * 64 + y) * 64;
                v = *(const __half2*)(base + (62 - x0 - 2 * txp));
                v = __halves2half2(__high2half(v), __low2half(v));   // -> {x even, x odd}
            } else {
                const __half* base = g_projh + ((size_t)(b * 256 + (c - 256)) * 64 + y) * 64;
                v = *(const __half2*)(base + (x0 + 2 * txp));
            }
            *(__half2*)&tile[cl][2 * txp] = v;
        }
    }
    __syncthreads();

    // store: each thread 2 iterations of one half2 (2 channels, 1 x)
#pragma unroll
    for (int it = 0; it < 2; it++) {
        int idx = tid + it * 256;          // 0..511
        int x = idx >> 4;                  // 0..31
        int pr = idx & 15;                 // channel pair
        __half2 v = __halves2half2(tile[2 * pr][x], tile[2 * pr + 1][x]);
        size_t a = ((size_t)b * PP + (y + 1) * PDIM + (x0 + x + 1)) * 512 + c0 + 2 * pr;
        *(__half2*)(g_xh + a) = v;
    }
}

// ---------------- proj GEMM: mma.sync fp16 2-term (Wh+Wl)·Fh ---------------
#define PJ_NCH 8
#define PJ_ASTR 40
#define PJ_BSTR 136
#define PJ_A_BYTES (128 * PJ_ASTR * 2)
#define PJ_B_BYTES (32 * PJ_BSTR * 2)
#define PJ_STAGE (2 * PJ_A_BYTES + PJ_B_BYTES)
#define PJ_SMEM (2 * PJ_STAGE)

__global__ void __launch_bounds__(256, 1)
proj_tc_kernel()
{
    extern __shared__ char smem[];
    const uint32_t sbase = smem_to_u32(smem);
    const int tid = threadIdx.x;
    const int lane = tid & 31;
    const int wid = tid >> 5;

    const int n0 = blockIdx.x * 128;
    const int m0 = blockIdx.y * 128;
    const int bb = n0 >> 12;
    const int hw0 = n0 & 4095;
    const int wm = (wid >> 2) * 64;
    const int wn = (wid & 3) * 32;

    const __half* wh = g_w1h + (size_t)m0 * C;
    const __half* wl = g_w1l + (size_t)m0 * C;
    const __half* fh = g_fh + (size_t)bb * CHW + hw0;

    float acc[4][4][4];
#pragma unroll
    for (int i = 0; i < 4; i++)
#pragma unroll
        for (int j = 0; j < 4; j++)
#pragma unroll
            for (int t = 0; t < 4; t++) acc[i][j][t] = 0.0f;

    auto load_chunk = [&](int st, int kt) {
        const uint32_t s = sbase + st * PJ_STAGE;
        const int k0 = kt * 32;
#pragma unroll
        for (int i = 0; i < 2; i++) {
            int idx = i * 256 + tid;
            int r = idx >> 2, kseg = idx & 3;
            size_t go = (size_t)r * C + k0 + kseg * 8;
            uint32_t so = (uint32_t)(r * PJ_ASTR + kseg * 8) * 2;
            cp16(s + so, wh + go);
            cp16(s + PJ_A_BYTES + so, wl + go);
        }
#pragma unroll
        for (int i = 0; i < 2; i++) {
            int idx = i * 256 + tid;
            int kr = idx >> 4, nseg = idx & 15;
            size_t go = (size_t)(k0 + kr) * HW + nseg * 8;
            uint32_t so = (uint32_t)(kr * PJ_BSTR + nseg * 8) * 2;
            cp16(s + 2 * PJ_A_BYTES + so, fh + go);
        }
        CP_COMMIT();
    };

    load_chunk(0, 0);

    for (int kt = 0; kt < PJ_NCH; kt++) {
        const int st = kt & 1;
        if (kt + 1 < PJ_NCH) { load_chunk(st ^ 1, kt + 1); CP_WAIT(1); }
        else                 { CP_WAIT(0); }
        __syncthreads();

        const uint32_t sAh = sbase + st * PJ_STAGE;
        const uint32_t sAl = sAh + PJ_A_BYTES;
        const uint32_t sBh = sAh + 2 * PJ_A_BYTES;

#pragma unroll
        for (int ks = 0; ks < 2; ks++) {
            uint32_t ah[4][4], al[4][4], bh[4][2];

            const int arow = wm + (lane & 15);
            const int acol = ks * 16 + ((lane >> 4) << 3);
#pragma unroll
            for (int tm = 0; tm < 4; tm++) {
                uint32_t ao = (uint32_t)((arow + tm * 16) * PJ_ASTR + acol) * 2;
                ldsm4(ah[tm], sAh + ao);
                ldsm4(al[tm], sAl + ao);
            }
            const int bkrow = ks * 16 + (lane & 15);
#pragma unroll
            for (int ng = 0; ng < 2; ng++) {
                const int bcol = wn + ng * 16 + ((lane >> 4) << 3);
                uint32_t bo = (uint32_t)(bkrow * PJ_BSTR + bcol) * 2;
                uint32_t t[4];
                ldsm4t(t, sBh + bo);
                bh[2*ng][0] = t[0]; bh[2*ng][1] = t[1];
                bh[2*ng+1][0] = t[2]; bh[2*ng+1][1] = t[3];
            }
#pragma unroll
            for (int tm = 0; tm < 4; tm++)
#pragma unroll
                for (int tn = 0; tn < 4; tn++) {
                    mma_fp(acc[tm][tn], ah[tm], bh[tn]);
                    mma_fp(acc[tm][tn], al[tm], bh[tn]);
                }
        }
        __syncthreads();
    }

    const int rowl = lane >> 2;
    const int colp = (lane & 3) * 2;
#pragma unroll
    for (int tm = 0; tm < 4; tm++) {
#pragma unroll
        for (int half = 0; half < 2; half++) {
            const int m = m0 + wm + tm * 16 + rowl + half * 8;
            const float add = g_add1[m];
            __half* ob = g_projh + ((size_t)bb * C + m) * HW + hw0 + wn + colp;
#pragma unroll
            for (int tn = 0; tn < 4; tn++) {
                float2 r;
                r.x = acc[tm][tn][half * 2 + 0] + add;
                r.y = acc[tm][tn][half * 2 + 1] + add;
                *(__half2*)(ob + tn * 8) = __float22half2_rn(r);
            }
        }
    }
}

// ---------------- offset conv as tensor-core GEMM (fp16 single, 3-stage) ---
#define OC_ROWS 396
#define OC_BSTR 40
#define OC_ASTR 40
#define OC_B_BYTES (OC_ROWS * OC_BSTR * 2)
#define OC_A_BYTES (9 * 32 * OC_ASTR * 2)
#define OC_STAGE (OC_B_BYTES + OC_A_BYTES)
#define OC_SMEM (3 * OC_STAGE)

__global__ void __launch_bounds__(256, 1)
off_gemm_kernel(const float* __restrict__ off_b)
{
    extern __shared__ char smem[];
    const uint32_t sbase = smem_to_u32(smem);
    const int tid = threadIdx.x;
    const int lane = tid & 31;
    const int wid = tid >> 5;

    const int n0 = blockIdx.x * 256;
    const int bb = n0 >> 12;
    const int hw0 = n0 & 4095;
    const int h0 = hw0 >> 6;

    const int wm = (wid >> 2) * 16;
    const int wn = (wid & 3) * 64;

    const size_t pbase = (size_t)bb * PP + h0 * PDIM;

    uint32_t rowb[8];
#pragma unroll
    for (int nt = 0; nt < 8; nt++) {
        int nl = wn + nt * 8 + (lane >> 2);
        int row = ((nl >> 6) + 1) * PDIM + (nl & 63) + 1;
        rowb[nt] = (uint32_t)(row * OC_BSTR + (lane & 3) * 2) * 2;
    }
    const int am = wm + (lane & 15);
    const int acol2 = (lane >> 4) << 3;

    float acc[8][4];
#pragma unroll
    for (int i = 0; i < 8; i++)
#pragma unroll
        for (int j = 0; j < 4; j++) acc[i][j] = 0.0f;

    auto load_chunk = [&](int st, int kc) {
        const uint32_t s = sbase + st * OC_STAGE;
        const int k0 = kc * 32;
#pragma unroll
        for (int i = 0; i < 7; i++) {
            int idx = i * 256 + tid;
            if (idx < 1584) {
                int r = idx >> 2, c4 = idx & 3;
                size_t go = (pbase + r) * 512 + k0 + c4 * 8;
                uint32_t so = (uint32_t)(r * OC_BSTR + c4 * 8) * 2;
                cp16(s + so, g_xh + go);
            }
        }
#pragma unroll
        for (int i = 0; i < 5; i++) {
            int idx = i * 256 + tid;
            if (idx < 1152) {
                int r = idx >> 2, c4 = idx & 3;
                size_t go = (size_t)r * 512 + k0 + c4 * 8;
                uint32_t so = (uint32_t)(r * OC_ASTR + c4 * 8) * 2;
                cp16(s + OC_B_BYTES + so, g_owh + go);
            }
        }
        CP_COMMIT();
    };

    const int stapB[9] = {(-PDIM-1)*OC_BSTR*2, (-PDIM)*OC_BSTR*2, (-PDIM+1)*OC_BSTR*2,
                          (-1)*OC_BSTR*2, 0, (1)*OC_BSTR*2,
                          (PDIM-1)*OC_BSTR*2, (PDIM)*OC_BSTR*2, (PDIM+1)*OC_BSTR*2};

    load_chunk(0, 0);
    load_chunk(1, 1);

    int st = 0;
    for (int kc = 0; kc < 16; kc++) {
        if (kc + 2 < 16) load_chunk((st + 2) % 3, kc + 2);
        else             CP_COMMIT();
        CP_WAIT(2);
        __syncthreads();

        const uint32_t sB  = sbase + st * OC_STAGE;
        const uint32_t sAh = sB + OC_B_BYTES;

#pragma unroll
        for (int tap = 0; tap < 9; tap++) {
            const int sb_t = stapB[tap];
#pragma unroll
            for (int ks = 0; ks < 2; ks++) {
                uint32_t ah[4];
                uint32_t ao = (uint32_t)((tap * 32 + am) * OC_ASTR + ks * 16 + acol2) * 2;
                ldsm4(ah, sAh + ao);
#pragma unroll
                for (int nt = 0; nt < 8; nt++) {
                    uint32_t base = sB + rowb[nt] + sb_t + ks * 32;
                    uint32_t b[2];
                    b[0] = lds32(base);
                    b[1] = lds32(base + 16);
                    mma_fp(acc[nt], ah, b);
                }
            }
        }
        __syncthreads();
        st = (st + 1) % 3;
    }

    const int mr = wm + (lane >> 2);
    const int cb = hw0 + wn + (lane & 3) * 2;
#pragma unroll
    for (int half = 0; half < 2; half++) {
        int m = mr + half * 8;
        if (m < 27) {
            float bias = off_b[m];
            float* ob = g_off + ((size_t)(bb * 27 + m)) * HW + cb;
#pragma unroll
            for (int nt = 0; nt < 8; nt++) {
                float2 r;
                r.x = acc[nt][half * 2 + 0] + bias;
                r.y = acc[nt][half * 2 + 1] + bias;
                *(float2*)(ob + nt * 8) = r;
            }
        }
    }
}

// ---------------- sampling v2: channel-contiguous gathers from g_xh --------
#define SP_PITCH 258

__global__ void __launch_bounds__(256)
sample_v2_kernel()
{
    __shared__ __half tile[64 * SP_PITCH];
    __shared__ float s_w[4][64];
    __shared__ int   s_a[4][64];

    const int tid = threadIdx.x;
    const int h = blockIdx.x;
    const int k = blockIdx.y;
    const int b = blockIdx.z;

    if (tid < 64) {
        const int w = tid;
        const int hw = h * W + w;
        const size_t obase = (size_t)(b * 27) * HW + hw;
        const float dy = g_off[obase + (size_t)k * HW];
        const float dx = g_off[obase + (size_t)(9 + k) * HW];
        const float mr = g_off[obase + (size_t)(18 + k) * HW];
        const float m  = 1.0f / (1.0f + expf(-mr));

        const int ky = k / 3 - 1, kx = k % 3 - 1;
        const float py = (float)(h + ky) + dy;
        const float px = (float)(w + kx) + dx;

        const float y0f = floorf(py), x0f = floorf(px);
        const float wy = py - y0f, wx = px - x0f;
        const int y0 = (int)y0f, x0 = (int)x0f;
        const int y1 = y0 + 1,   x1 = x0 + 1;

        const bool vy0 = (y0 >= 0) && (y0 < H);
        const bool vy1 = (y1 >= 0) && (y1 < H);
        const bool vx0 = (x0 >= 0) && (x0 < W);
        const bool vx1 = (x1 >= 0) && (x1 < W);

        s_w[0][w] = (1.0f - wy) * (1.0f - wx) * ((vy0 && vx0) ? m : 0.0f);
        s_w[1][w] = (1.0f - wy) * wx          * ((vy0 && vx1) ? m : 0.0f);
        s_w[2][w] = wy * (1.0f - wx)          * ((vy1 && vx0) ? m : 0.0f);
        s_w[3][w] = wy * wx                   * ((vy1 && vx1) ? m : 0.0f);

        const int yc0 = min(max(y0, 0), H - 1);
        const int yc1 = min(max(y1, 0), H - 1);
        const int xc0 = min(max(x0, 0), W - 1);
        const int xc1 = min(max(x1, 0), W - 1);

        s_a[0][w] = (yc0 + 1) * PDIM + xc0 + 1;
        s_a[1][w] = (yc0 + 1) * PDIM + xc1 + 1;
        s_a[2][w] = (yc1 + 1) * PDIM + xc0 + 1;
        s_a[3][w] = (yc1 + 1) * PDIM + xc1 + 1;
    }
    __syncthreads();

    const __half* xb = g_xh + (size_t)b * PP * 512;
    const int cpair = tid & 127;
    const int pxg = tid >> 7;

    for (int px = pxg; px < 64; px += 2) {
        const float w00 = s_w[0][px], w01 = s_w[1][px];
        const float w10 = s_w[2][px], w11 = s_w[3][px];
        const __half2 f00 = *((const __half2*)(xb + (size_t)s_a[0][px] * 512) + cpair);
        const __half2 f01 = *((const __half2*)(xb + (size_t)s_a[1][px] * 512) + cpair);
        const __half2 f10 = *((const __half2*)(xb + (size_t)s_a[2][px] * 512) + cpair);
        const __half2 f11 = *((const __half2*)(xb + (size_t)s_a[3][px] * 512) + cpair);
        float2 a = __half22float2(f00), bq = __half22float2(f01);
        float2 c2 = __half22float2(f10), d = __half22float2(f11);
        float2 r;
        r.x = w00 * a.x + w01 * bq.x + w10 * c2.x + w11 * d.x;
        r.y = w00 * a.y + w01 * bq.y + w10 * c2.y + w11 * d.y;
        *(__half2*)&tile[px * SP_PITCH + 2 * cpair] = __float22half2_rn(r);
    }
    __syncthreads();

    const int lane = tid & 31, wid = tid >> 5;
    const size_t outb = (size_t)b * HW + h * 64 + 2 * lane;
#pragma unroll 4
    for (int i = 0; i < 32; i++) {
        const int c = wid * 32 + i;
        __half v0 = tile[(2 * lane)     * SP_PITCH + c];
        __half v1 = tile[(2 * lane + 1) * SP_PITCH + c];
        *(__half2*)(g_colh + ((size_t)c * KK + k) * NPIX + outb) = __halves2half2(v0, v1);
    }
}

// ---------------- DCN GEMM: mma.sync fp16 single-term, 3-stage, M=128 ------
#define DCN_NCH 72
#define A_STRIDE 40
#define B_STRIDE 136
#define A_BYTES (128 * A_STRIDE * 2)
#define B_BYTES (32 * B_STRIDE * 2)
#define STAGE_BYTES (A_BYTES + B_BYTES)
#define DCN_SMEM (3 * STAGE_BYTES)

__global__ void __launch_bounds__(256, 1)
dcn_gemm_kernel(float* __restrict__ out)
{
    extern __shared__ char smem[];
    const uint32_t sbase = smem_to_u32(smem);
    const int tid = threadIdx.x;
    const int lane = tid & 31;
    const int wid = tid >> 5;

    const int n0 = blockIdx.x * 128;
    const int m0 = blockIdx.y * 128;
    const int bb = n0 >> 12;
    const int hw0 = n0 & 4095;
    const int wm = (wid >> 2) * 64;
    const int wn = (wid & 3) * 32;

    const __half* wh = g_wh + (size_t)m0 * CK;

    float acc[4][4][4];
#pragma unroll
    for (int i = 0; i < 4; i++)
#pragma unroll
        for (int j = 0; j < 4; j++)
#pragma unroll
            for (int t = 0; t < 4; t++) acc[i][j][t] = 0.0f;

    auto load_chunk = [&](int st, int kt) {
        const uint32_t s = sbase + st * STAGE_BYTES;
        const int k0 = kt * 32;
#pragma unroll
        for (int i = 0; i < 2; i++) {
            int idx = i * 256 + tid;
            int r = idx >> 2, kseg = idx & 3;
            size_t go = (size_t)r * CK + k0 + kseg * 8;
            uint32_t so = (uint32_t)(r * A_STRIDE + kseg * 8) * 2;
            cp16(s + so, wh + go);
        }
#pragma unroll
        for (int i = 0; i < 2; i++) {
            int idx = i * 256 + tid;
            int kr = idx >> 4, nseg = idx & 15;
            size_t go = (size_t)(k0 + kr) * NPIX + n0 + nseg * 8;
            uint32_t so = (uint32_t)(kr * B_STRIDE + nseg * 8) * 2;
            cp16(s + A_BYTES + so, g_colh + go);
        }
        CP_COMMIT();
    };

    load_chunk(0, 0);
    load_chunk(1, 1);

    int st = 0;
    for (int kt = 0; kt < DCN_NCH; kt++) {
        if (kt + 2 < DCN_NCH) load_chunk((st + 2) % 3, kt + 2);
        else                  CP_COMMIT();
        CP_WAIT(2);
        __syncthreads();

        const uint32_t sA = sbase + st * STAGE_BYTES;
        const uint32_t sB = sA + A_BYTES;

#pragma unroll
        for (int ks = 0; ks < 2; ks++) {
            uint32_t ah[4][4], bf[4][2];

            const int arow = wm + (lane & 15);
            const int acol = ks * 16 + ((lane >> 4) << 3);
#pragma unroll
            for (int tm = 0; tm < 4; tm++) {
                uint32_t ao = (uint32_t)((arow + tm * 16) * A_STRIDE + acol) * 2;
                ldsm4(ah[tm], sA + ao);
            }
            const int bkrow = ks * 16 + (lane & 15);
#pragma unroll
            for (int ng = 0; ng < 2; ng++) {
                const int bcol = wn + ng * 16 + ((lane >> 4) << 3);
                uint32_t bo = (uint32_t)(bkrow * B_STRIDE + bcol) * 2;
                uint32_t t[4];
                ldsm4t(t, sB + bo);
                bf[2*ng][0] = t[0]; bf[2*ng][1] = t[1];
                bf[2*ng+1][0] = t[2]; bf[2*ng+1][1] = t[3];
            }
#pragma unroll
            for (int tm = 0; tm < 4; tm++)
#pragma unroll
                for (int tn = 0; tn < 4; tn++)
                    mma_fp(acc[tm][tn], ah[tm], bf[tn]);
        }
        __syncthreads();
        st = (st + 1) % 3;
    }

    const int rowl = lane >> 2;
    const int colp = (lane & 3) * 2;
#pragma unroll
    for (int tm = 0; tm < 4; tm++) {
#pragma unroll
        for (int half = 0; half < 2; half++) {
            const int m = m0 + wm + tm * 16 + rowl + half * 8;
            const float add = g_add2[m];
            const __half* pr = g_projh + ((size_t)bb * C + m) * HW + hw0 + wn + colp;
            float*        ob = out     + ((size_t)bb * C + m) * HW + hw0 + wn + colp;
#pragma unroll
            for (int tn = 0; tn < 4; tn++) {
                float2 p = __half22float2(*(const __half2*)(pr + tn * 8));
                float2 r;
                r.x = fmaxf(acc[tm][tn][half * 2 + 0] + add + p.x, 0.0f);
                r.y = fmaxf(acc[tm][tn][half * 2 + 1] + add + p.y, 0.0f);
                *(float2*)(ob + tn * 8) = r;
            }
        }
    }
}

// ---------------- launch ----------------------------------------------------
extern "C" void kernel_launch(void* const* d_in, const int* in_sizes, int n_in,
                              void* d_out, int out_size)
{
    const float* feature = (const float*)d_in[0];
    const float* p1_w    = (const float*)d_in[1];
    const float* p1_b    = (const float*)d_in[2];
    const float* bn1_g   = (const float*)d_in[3];
    const float* bn1_b   = (const float*)d_in[4];
    const float* bn1_m   = (const float*)d_in[5];
    const float* bn1_v   = (const float*)d_in[6];
    const float* off_w   = (const float*)d_in[7];
    const float* off_b   = (const float*)d_in[8];
    const float* dcn_w   = (const float*)d_in[9];
    const float* dcn_b   = (const float*)d_in[10];
    const float* bn2_g   = (const float*)d_in[11];
    const float* bn2_b   = (const float*)d_in[12];
    const float* bn2_m   = (const float*)d_in[13];
    const float* bn2_v   = (const float*)d_in[14];

    cudaFuncSetAttribute(dcn_gemm_kernel,
                         cudaFuncAttributeMaxDynamicSharedMemorySize, DCN_SMEM);
    cudaFuncSetAttribute(off_gemm_kernel,
                         cudaFuncAttributeMaxDynamicSharedMemorySize, OC_SMEM);
    cudaFuncSetAttribute(proj_tc_kernel,
                         cudaFuncAttributeMaxDynamicSharedMemorySize, PJ_SMEM);

    prep_small_kernel<<<PS_TOTAL, 256>>>(p1_w, p1_b, bn1_g, bn1_b, bn1_m, bn1_v,
                                         off_w, dcn_w, dcn_b,
                                         bn2_g, bn2_b, bn2_m, bn2_v);
    conv_f16_kernel<<<(int)((size_t)BATCH * CHW / 2048), 256>>>(feature);

    proj_tc_kernel<<<dim3(NPIX / 128, 2), 256, PJ_SMEM>>>();

    pack_kernel<<<dim3(2, 16, 512), 256>>>();

    off_gemm_kernel<<<NPIX / 256, 256, OC_SMEM>>>(off_b);

    sample_v2_kernel<<<dim3(H, KK, BATCH), 256>>>();

    dcn_gemm_kernel<<<dim3(NPIX / 128, C / 128), 256, DCN_SMEM>>>((float*)d_out);
}

// round 17
// speedup vs baseline: 1.1063x; 1.0624x over previous
#include <cuda_runtime.h>
#include <cuda_bf16.h>
#include <cuda_fp16.h>
#include <math.h>
#include <stdint.h>

// Problem constants
#define BATCH 8
#define C 256
#define H 64
#define W 64
#define HW 4096
#define NPIX 32768
#define KK 9
#define CK 2304
#define CHW (C*HW)
#define PDIM 66
#define PP (PDIM*PDIM)

// ---------------- scratch (device globals; no allocation) ----------------
__device__ __half g_projh[(size_t)BATCH * CHW];          // proj in fp16
__device__ float g_off[(size_t)BATCH * 27 * HW];
__device__ __half g_colh[(size_t)CK * NPIX];
__device__ __half g_wh[(size_t)C * CK];
__device__ __half g_xh[(size_t)BATCH * PP * 512];
__device__ __half g_owh[(size_t)9 * 32 * 512];
__device__ __half g_fh[(size_t)BATCH * CHW];
__device__ __half g_w1h[(size_t)C * C];
__device__ __half g_w1l[(size_t)C * C];
__device__ float g_inv1[C], g_add1[C], g_inv2[C], g_add2[C];

// ================= mma.sync / ldmatrix / cp.async helpers =================
__device__ __forceinline__ uint32_t smem_to_u32(const void* p) {
    uint32_t a;
    asm("{ .reg .u64 t; cvta.to.shared.u64 t, %1; cvt.u32.u64 %0, t; }" : "=r"(a) : "l"(p));
    return a;
}
__device__ __forceinline__ void cp16(uint32_t s, const void* g) {
    asm volatile("cp.async.cg.shared.global [%0], [%1], 16;" :: "r"(s), "l"(g));
}
#define CP_COMMIT() asm volatile("cp.async.commit_group;" ::: "memory")
#define CP_WAIT(n)  asm volatile("cp.async.wait_group %0;" :: "n"(n) : "memory")

__device__ __forceinline__ void ldsm4(uint32_t* r, uint32_t addr) {
    asm volatile("ldmatrix.sync.aligned.m8n8.x4.shared.b16 {%0,%1,%2,%3}, [%4];"
        : "=r"(r[0]), "=r"(r[1]), "=r"(r[2]), "=r"(r[3]) : "r"(addr));
}
__device__ __forceinline__ void ldsm4t(uint32_t* r, uint32_t addr) {
    asm volatile("ldmatrix.sync.aligned.m8n8.x4.trans.shared.b16 {%0,%1,%2,%3}, [%4];"
        : "=r"(r[0]), "=r"(r[1]), "=r"(r[2]), "=r"(r[3]) : "r"(addr));
}
__device__ __forceinline__ uint32_t lds32(uint32_t addr) {
    uint32_t v;
    asm volatile("ld.shared.b32 %0, [%1];" : "=r"(v) : "r"(addr));
    return v;
}
__device__ __forceinline__ void mma_fp(float* c, const uint32_t* a, const uint32_t* b) {
    asm volatile("mma.sync.aligned.m16n8k16.row.col.f32.f16.f16.f32 "
        "{%0,%1,%2,%3}, {%4,%5,%6,%7}, {%8,%9}, {%0,%1,%2,%3};"
        : "+f"(c[0]), "+f"(c[1]), "+f"(c[2]), "+f"(c[3])
        : "r"(a[0]), "r"(a[1]), "r"(a[2]), "r"(a[3]), "r"(b[0]), "r"(b[1]));
}

// ---------------- merged small prep (region-dispatched) --------------------
#define PS_SW1   1
#define PS_SW1E  (PS_SW1 + 2304)
#define PS_W1E   (PS_SW1E + 256)
#define PS_OWE   (PS_W1E + 576)
#define PS_TOTAL (PS_OWE + 4160)

__global__ void __launch_bounds__(256)
prep_small_kernel(const float* __restrict__ p1_w,  const float* __restrict__ p1_b,
                  const float* __restrict__ bn1_g, const float* __restrict__ bn1_b,
                  const float* __restrict__ bn1_m, const float* __restrict__ bn1_v,
                  const float* __restrict__ off_w,
                  const float* __restrict__ dcn_w, const float* __restrict__ dcn_b,
                  const float* __restrict__ bn2_g, const float* __restrict__ bn2_b,
                  const float* __restrict__ bn2_m, const float* __restrict__ bn2_v)
{
    const int bx = blockIdx.x;
    const int tid = threadIdx.x;

    if (bx == 0) {
        int o = tid;
        if (o < C) {
            float inv1 = bn1_g[o] * rsqrtf(bn1_v[o] + 1e-5f);
            g_inv1[o] = inv1;
            g_add1[o] = bn1_b[o] - bn1_m[o] * inv1 + p1_b[o] * inv1;
            float inv2 = bn2_g[o] * rsqrtf(bn2_v[o] + 1e-5f);
            g_inv2[o] = inv2;
            g_add2[o] = bn2_b[o] - bn2_m[o] * inv2 + dcn_b[o] * inv2;
        }
        return;
    }
    if (bx < PS_SW1E) {
        int idx = (bx - PS_SW1) * 256 + tid;
        if (idx < C * CK) {
            int o = idx / CK;
            float inv2 = bn2_g[o] * rsqrtf(bn2_v[o] + 1e-5f);
            g_wh[idx] = __float2half(dcn_w[idx] * inv2);
        }
        return;
    }
    if (bx < PS_W1E) {
        int idx = (bx - PS_SW1E) * 256 + tid;
        int o = idx >> 8;
        float inv1 = bn1_g[o] * rsqrtf(bn1_v[o] + 1e-5f);
        float v = p1_w[idx] * inv1;
        __half hi = __float2half(v);
        g_w1h[idx] = hi;
        g_w1l[idx] = __float2half(v - __half2float(hi));
        return;
    }
    if (bx < PS_OWE) {
        int idx = (bx - PS_W1E) * 256 + tid;
        int t = idx >> 14;
        int r = (idx >> 9) & 31;
        int c = idx & 511;
        float v = 0.0f;
        if (r < 27) {
            int kh = t / 3, kw = t % 3;
            v = off_w[((size_t)(r * 512 + c) * 3 + kh) * 3 + kw];
        }
        g_owh[idx] = __float2half(v);
        return;
    }
    {
        int idx = (bx - PS_OWE) * 256 + tid;
        if (idx < BATCH * 260 * 512) {
            int c = idx & 511;
            int rest = idx >> 9;
            int pos = rest % 260;
            int b = rest / 260;
            int yp, xp;
            if (pos < 66)       { yp = 0;  xp = pos; }
            else if (pos < 132) { yp = 65; xp = pos - 66; }
            else {
                int i = pos - 132;
                yp = 1 + (i >> 1);
                xp = (i & 1) * 65;
            }
            size_t a = ((size_t)b * PP + yp * PDIM + xp) * 512 + c;
            g_xh[a] = __float2half(0.0f);
        }
    }
}

// feature -> fp16, vectorized x8 (2x LDG.128, 1x STG.128 per thread)
__global__ void conv_f16_kernel(const float* __restrict__ feature)
{
    size_t i8 = ((size_t)blockIdx.x * 256 + threadIdx.x) * 8;
    float4 a = *(const float4*)(feature + i8);
    float4 b = *(const float4*)(feature + i8 + 4);
    __half2 h[4];
    h[0] = __floats2half2_rn(a.x, a.y);
    h[1] = __floats2half2_rn(a.z, a.w);
    h[2] = __floats2half2_rn(b.x, b.y);
    h[3] = __floats2half2_rn(b.z, b.w);
    *(uint4*)(g_fh + i8) = *(uint4*)h;
}

// pack v2: half2 everywhere; concat(flip(g_fh), g_projh) -> X^T fp16
__global__ void __launch_bounds__(256)
pack_kernel()
{
    __shared__ __half tile[32][36];
    const int tid = threadIdx.x;
    const int b = blockIdx.z >> 6;
    const int y = blockIdx.z & 63;
    const int x0 = blockIdx.x * 32;
    const int c0 = blockIdx.y * 32;

    {
        const int txp = tid & 15;
        const int crow = tid >> 4;
#pragma unroll
        for (int j = 0; j < 2; j++) {
            int cl = crow + j * 16;
            int c = c0 + cl;
            __half2 v;
            if (c < 256) {
                const __half* base = g_fh + ((size_t)(b * 256 + c) * 64 + y) * 64;
                v = *(const __half2*)(base + (62 - x0 - 2 * txp));
                v = __halves2half2(__high2half(v), __low2half(v));
            } else {
                const __half* base = g_projh + ((size_t)(b * 256 + (c - 256)) * 64 + y) * 64;
                v = *(const __half2*)(base + (x0 + 2 * txp));
            }
            *(__half2*)&tile[cl][2 * txp] = v;
        }
    }
    __syncthreads();

#pragma unroll
    for (int it = 0; it < 2; it++) {
        int idx = tid + it * 256;
        int x = idx >> 4;
        int pr = idx & 15;
        __half2 v = __halves2half2(tile[2 * pr][x], tile[2 * pr + 1][x]);
        size_t a = ((size_t)b * PP + (y + 1) * PDIM + (x0 + x + 1)) * 512 + c0 + 2 * pr;
        *(__half2*)(g_xh + a) = v;
    }
}

// ---------------- proj GEMM: mma.sync fp16 2-term (Wh+Wl)·Fh ---------------
#define PJ_NCH 8
#define PJ_ASTR 40
#define PJ_BSTR 136
#define PJ_A_BYTES (128 * PJ_ASTR * 2)
#define PJ_B_BYTES (32 * PJ_BSTR * 2)
#define PJ_STAGE (2 * PJ_A_BYTES + PJ_B_BYTES)
#define PJ_SMEM (2 * PJ_STAGE)

__global__ void __launch_bounds__(256, 1)
proj_tc_kernel()
{
    extern __shared__ char smem[];
    const uint32_t sbase = smem_to_u32(smem);
    const int tid = threadIdx.x;
    const int lane = tid & 31;
    const int wid = tid >> 5;

    const int n0 = blockIdx.x * 128;
    const int m0 = blockIdx.y * 128;
    const int bb = n0 >> 12;
    const int hw0 = n0 & 4095;
    const int wm = (wid >> 2) * 64;
    const int wn = (wid & 3) * 32;

    const __half* wh = g_w1h + (size_t)m0 * C;
    const __half* wl = g_w1l + (size_t)m0 * C;
    const __half* fh = g_fh + (size_t)bb * CHW + hw0;

    float acc[4][4][4];
#pragma unroll
    for (int i = 0; i < 4; i++)
#pragma unroll
        for (int j = 0; j < 4; j++)
#pragma unroll
            for (int t = 0; t < 4; t++) acc[i][j][t] = 0.0f;

    auto load_chunk = [&](int st, int kt) {
        const uint32_t s = sbase + st * PJ_STAGE;
        const int k0 = kt * 32;
#pragma unroll
        for (int i = 0; i < 2; i++) {
            int idx = i * 256 + tid;
            int r = idx >> 2, kseg = idx & 3;
            size_t go = (size_t)r * C + k0 + kseg * 8;
            uint32_t so = (uint32_t)(r * PJ_ASTR + kseg * 8) * 2;
            cp16(s + so, wh + go);
            cp16(s + PJ_A_BYTES + so, wl + go);
        }
#pragma unroll
        for (int i = 0; i < 2; i++) {
            int idx = i * 256 + tid;
            int kr = idx >> 4, nseg = idx & 15;
            size_t go = (size_t)(k0 + kr) * HW + nseg * 8;
            uint32_t so = (uint32_t)(kr * PJ_BSTR + nseg * 8) * 2;
            cp16(s + 2 * PJ_A_BYTES + so, fh + go);
        }
        CP_COMMIT();
    };

    load_chunk(0, 0);

    for (int kt = 0; kt < PJ_NCH; kt++) {
        const int st = kt & 1;
        if (kt + 1 < PJ_NCH) { load_chunk(st ^ 1, kt + 1); CP_WAIT(1); }
        else                 { CP_WAIT(0); }
        __syncthreads();

        const uint32_t sAh = sbase + st * PJ_STAGE;
        const uint32_t sAl = sAh + PJ_A_BYTES;
        const uint32_t sBh = sAh + 2 * PJ_A_BYTES;

#pragma unroll
        for (int ks = 0; ks < 2; ks++) {
            uint32_t ah[4][4], al[4][4], bh[4][2];

            const int arow = wm + (lane & 15);
            const int acol = ks * 16 + ((lane >> 4) << 3);
#pragma unroll
            for (int tm = 0; tm < 4; tm++) {
                uint32_t ao = (uint32_t)((arow + tm * 16) * PJ_ASTR + acol) * 2;
                ldsm4(ah[tm], sAh + ao);
                ldsm4(al[tm], sAl + ao);
            }
            const int bkrow = ks * 16 + (lane & 15);
#pragma unroll
            for (int ng = 0; ng < 2; ng++) {
                const int bcol = wn + ng * 16 + ((lane >> 4) << 3);
                uint32_t bo = (uint32_t)(bkrow * PJ_BSTR + bcol) * 2;
                uint32_t t[4];
                ldsm4t(t, sBh + bo);
                bh[2*ng][0] = t[0]; bh[2*ng][1] = t[1];
                bh[2*ng+1][0] = t[2]; bh[2*ng+1][1] = t[3];
            }
#pragma unroll
            for (int tm = 0; tm < 4; tm++)
#pragma unroll
                for (int tn = 0; tn < 4; tn++) {
                    mma_fp(acc[tm][tn], ah[tm], bh[tn]);
                    mma_fp(acc[tm][tn], al[tm], bh[tn]);
                }
        }
        __syncthreads();
    }

    const int rowl = lane >> 2;
    const int colp = (lane & 3) * 2;
#pragma unroll
    for (int tm = 0; tm < 4; tm++) {
#pragma unroll
        for (int half = 0; half < 2; half++) {
            const int m = m0 + wm + tm * 16 + rowl + half * 8;
            const float add = g_add1[m];
            __half* ob = g_projh + ((size_t)bb * C + m) * HW + hw0 + wn + colp;
#pragma unroll
            for (int tn = 0; tn < 4; tn++) {
                float2 r;
                r.x = acc[tm][tn][half * 2 + 0] + add;
                r.y = acc[tm][tn][half * 2 + 1] + add;
                *(__half2*)(ob + tn * 8) = __float22half2_rn(r);
            }
        }
    }
}

// ---------------- offset conv as tensor-core GEMM (fp16 single, 3-stage) ---
#define OC_ROWS 396
#define OC_BSTR 40
#define OC_ASTR 40
#define OC_B_BYTES (OC_ROWS * OC_BSTR * 2)
#define OC_A_BYTES (9 * 32 * OC_ASTR * 2)
#define OC_STAGE (OC_B_BYTES + OC_A_BYTES)
#define OC_SMEM (3 * OC_STAGE)

__global__ void __launch_bounds__(256, 1)
off_gemm_kernel(const float* __restrict__ off_b)
{
    extern __shared__ char smem[];
    const uint32_t sbase = smem_to_u32(smem);
    const int tid = threadIdx.x;
    const int lane = tid & 31;
    const int wid = tid >> 5;

    const int n0 = blockIdx.x * 256;
    const int bb = n0 >> 12;
    const int hw0 = n0 & 4095;
    const int h0 = hw0 >> 6;

    const int wm = (wid >> 2) * 16;
    const int wn = (wid & 3) * 64;

    const size_t pbase = (size_t)bb * PP + h0 * PDIM;

    uint32_t rowb[8];
#pragma unroll
    for (int nt = 0; nt < 8; nt++) {
        int nl = wn + nt * 8 + (lane >> 2);
        int row = ((nl >> 6) + 1) * PDIM + (nl & 63) + 1;
        rowb[nt] = (uint32_t)(row * OC_BSTR + (lane & 3) * 2) * 2;
    }
    const int am = wm + (lane & 15);
    const int acol2 = (lane >> 4) << 3;

    float acc[8][4];
#pragma unroll
    for (int i = 0; i < 8; i++)
#pragma unroll
        for (int j = 0; j < 4; j++) acc[i][j] = 0.0f;

    auto load_chunk = [&](int st, int kc) {
        const uint32_t s = sbase + st * OC_STAGE;
        const int k0 = kc * 32;
#pragma unroll
        for (int i = 0; i < 7; i++) {
            int idx = i * 256 + tid;
            if (idx < 1584) {
                int r = idx >> 2, c4 = idx & 3;
                size_t go = (pbase + r) * 512 + k0 + c4 * 8;
                uint32_t so = (uint32_t)(r * OC_BSTR + c4 * 8) * 2;
                cp16(s + so, g_xh + go);
            }
        }
#pragma unroll
        for (int i = 0; i < 5; i++) {
            int idx = i * 256 + tid;
            if (idx < 1152) {
                int r = idx >> 2, c4 = idx & 3;
                size_t go = (size_t)r * 512 + k0 + c4 * 8;
                uint32_t so = (uint32_t)(r * OC_ASTR + c4 * 8) * 2;
                cp16(s + OC_B_BYTES + so, g_owh + go);
            }
        }
        CP_COMMIT();
    };

    const int stapB[9] = {(-PDIM-1)*OC_BSTR*2, (-PDIM)*OC_BSTR*2, (-PDIM+1)*OC_BSTR*2,
                          (-1)*OC_BSTR*2, 0, (1)*OC_BSTR*2,
                          (PDIM-1)*OC_BSTR*2, (PDIM)*OC_BSTR*2, (PDIM+1)*OC_BSTR*2};

    load_chunk(0, 0);
    load_chunk(1, 1);

    int st = 0;
    for (int kc = 0; kc < 16; kc++) {
        if (kc + 2 < 16) load_chunk((st + 2) % 3, kc + 2);
        else             CP_COMMIT();
        CP_WAIT(2);
        __syncthreads();

        const uint32_t sB  = sbase + st * OC_STAGE;
        const uint32_t sAh = sB + OC_B_BYTES;

#pragma unroll
        for (int tap = 0; tap < 9; tap++) {
            const int sb_t = stapB[tap];
#pragma unroll
            for (int ks = 0; ks < 2; ks++) {
                uint32_t ah[4];
                uint32_t ao = (uint32_t)((tap * 32 + am) * OC_ASTR + ks * 16 + acol2) * 2;
                ldsm4(ah, sAh + ao);
#pragma unroll
                for (int nt = 0; nt < 8; nt++) {
                    uint32_t base = sB + rowb[nt] + sb_t + ks * 32;
                    uint32_t b[2];
                    b[0] = lds32(base);
                    b[1] = lds32(base + 16);
                    mma_fp(acc[nt], ah, b);
                }
            }
        }
        __syncthreads();
        st = (st + 1) % 3;
    }

    const int mr = wm + (lane >> 2);
    const int cb = hw0 + wn + (lane & 3) * 2;
#pragma unroll
    for (int half = 0; half < 2; half++) {
        int m = mr + half * 8;
        if (m < 27) {
            float bias = off_b[m];
            float* ob = g_off + ((size_t)(bb * 27 + m)) * HW + cb;
#pragma unroll
            for (int nt = 0; nt < 8; nt++) {
                float2 r;
                r.x = acc[nt][half * 2 + 0] + bias;
                r.y = acc[nt][half * 2 + 1] + bias;
                *(float2*)(ob + nt * 8) = r;
            }
        }
    }
}

// ---------------- sampling v3: uint4 (8-channel) gathers from g_xh ---------
#define SP_PITCH 258

__global__ void __launch_bounds__(256)
sample_v2_kernel()
{
    __shared__ __half tile[64 * SP_PITCH];
    __shared__ float s_w[4][64];
    __shared__ int   s_a[4][64];

    const int tid = threadIdx.x;
    const int h = blockIdx.x;
    const int k = blockIdx.y;
    const int b = blockIdx.z;

    if (tid < 64) {
        const int w = tid;
        const int hw = h * W + w;
        const size_t obase = (size_t)(b * 27) * HW + hw;
        const float dy = g_off[obase + (size_t)k * HW];
        const float dx = g_off[obase + (size_t)(9 + k) * HW];
        const float mr = g_off[obase + (size_t)(18 + k) * HW];
        const float m  = 1.0f / (1.0f + expf(-mr));

        const int ky = k / 3 - 1, kx = k % 3 - 1;
        const float py = (float)(h + ky) + dy;
        const float px = (float)(w + kx) + dx;

        const float y0f = floorf(py), x0f = floorf(px);
        const float wy = py - y0f, wx = px - x0f;
        const int y0 = (int)y0f, x0 = (int)x0f;
        const int y1 = y0 + 1,   x1 = x0 + 1;

        const bool vy0 = (y0 >= 0) && (y0 < H);
        const bool vy1 = (y1 >= 0) && (y1 < H);
        const bool vx0 = (x0 >= 0) && (x0 < W);
        const bool vx1 = (x1 >= 0) && (x1 < W);

        s_w[0][w] = (1.0f - wy) * (1.0f - wx) * ((vy0 && vx0) ? m : 0.0f);
        s_w[1][w] = (1.0f - wy) * wx          * ((vy0 && vx1) ? m : 0.0f);
        s_w[2][w] = wy * (1.0f - wx)          * ((vy1 && vx0) ? m : 0.0f);
        s_w[3][w] = wy * wx                   * ((vy1 && vx1) ? m : 0.0f);

        const int yc0 = min(max(y0, 0), H - 1);
        const int yc1 = min(max(y1, 0), H - 1);
        const int xc0 = min(max(x0, 0), W - 1);
        const int xc1 = min(max(x1, 0), W - 1);

        s_a[0][w] = (yc0 + 1) * PDIM + xc0 + 1;
        s_a[1][w] = (yc0 + 1) * PDIM + xc1 + 1;
        s_a[2][w] = (yc1 + 1) * PDIM + xc0 + 1;
        s_a[3][w] = (yc1 + 1) * PDIM + xc1 + 1;
    }
    __syncthreads();

    const __half* xb = g_xh + (size_t)b * PP * 512;
    const int cg = tid & 31;           // 8-channel group (channels cg*8..cg*8+7)
    const int pxg = tid >> 5;          // 0..7

#pragma unroll
    for (int i = 0; i < 8; i++) {
        const int px = pxg + i * 8;
        const float w00 = s_w[0][px], w01 = s_w[1][px];
        const float w10 = s_w[2][px], w11 = s_w[3][px];
        const uint4 f0 = *(const uint4*)(xb + (size_t)s_a[0][px] * 512 + cg * 8);
        const uint4 f1 = *(const uint4*)(xb + (size_t)s_a[1][px] * 512 + cg * 8);
        const uint4 f2 = *(const uint4*)(xb + (size_t)s_a[2][px] * 512 + cg * 8);
        const uint4 f3 = *(const uint4*)(xb + (size_t)s_a[3][px] * 512 + cg * 8);
        const __half2* a2 = (const __half2*)&f0;
        const __half2* b2 = (const __half2*)&f1;
        const __half2* c2 = (const __half2*)&f2;
        const __half2* d2 = (const __half2*)&f3;
        __half* trow = &tile[px * SP_PITCH + cg * 8];
#pragma unroll
        for (int j = 0; j < 4; j++) {
            float2 a = __half22float2(a2[j]), bq = __half22float2(b2[j]);
            float2 c = __half22float2(c2[j]), d = __half22float2(d2[j]);
            float2 r;
            r.x = w00 * a.x + w01 * bq.x + w10 * c.x + w11 * d.x;
            r.y = w00 * a.y + w01 * bq.y + w10 * c.y + w11 * d.y;
            *(__half2*)(trow + 2 * j) = __float22half2_rn(r);
        }
    }
    __syncthreads();

    const int lane = tid & 31, wid = tid >> 5;
    const size_t outb = (size_t)b * HW + h * 64 + 2 * lane;
#pragma unroll 4
    for (int i = 0; i < 32; i++) {
        const int c = wid * 32 + i;
        __half v0 = tile[(2 * lane)     * SP_PITCH + c];
        __half v1 = tile[(2 * lane + 1) * SP_PITCH + c];
        *(__half2*)(g_colh + ((size_t)c * KK + k) * NPIX + outb) = __halves2half2(v0, v1);
    }
}

// ---------------- DCN GEMM: mma.sync fp16 single-term, 3-stage, M=128 ------
#define DCN_NCH 72
#define A_STRIDE 40
#define B_STRIDE 136
#define A_BYTES (128 * A_STRIDE * 2)
#define B_BYTES (32 * B_STRIDE * 2)
#define STAGE_BYTES (A_BYTES + B_BYTES)
#define DCN_SMEM (3 * STAGE_BYTES)

__global__ void __launch_bounds__(256, 1)
dcn_gemm_kernel(float* __restrict__ out)
{
    extern __shared__ char smem[];
    const uint32_t sbase = smem_to_u32(smem);
    const int tid = threadIdx.x;
    const int lane = tid & 31;
    const int wid = tid >> 5;

    const int n0 = blockIdx.x * 128;
    const int m0 = blockIdx.y * 128;
    const int bb = n0 >> 12;
    const int hw0 = n0 & 4095;
    const int wm = (wid >> 2) * 64;
    const int wn = (wid & 3) * 32;

    const __half* wh = g_wh + (size_t)m0 * CK;

    float acc[4][4][4];
#pragma unroll
    for (int i = 0; i < 4; i++)
#pragma unroll
        for (int j = 0; j < 4; j++)
#pragma unroll
            for (int t = 0; t < 4; t++) acc[i][j][t] = 0.0f;

    auto load_chunk = [&](int st, int kt) {
        const uint32_t s = sbase + st * STAGE_BYTES;
        const int k0 = kt * 32;
#pragma unroll
        for (int i = 0; i < 2; i++) {
            int idx = i * 256 + tid;
            int r = idx >> 2, kseg = idx & 3;
            size_t go = (size_t)r * CK + k0 + kseg * 8;
            uint32_t so = (uint32_t)(r * A_STRIDE + kseg * 8) * 2;
            cp16(s + so, wh + go);
        }
#pragma unroll
        for (int i = 0; i < 2; i++) {
            int idx = i * 256 + tid;
            int kr = idx >> 4, nseg = idx & 15;
            size_t go = (size_t)(k0 + kr) * NPIX + n0 + nseg * 8;
            uint32_t so = (uint32_t)(kr * B_STRIDE + nseg * 8) * 2;
            cp16(s + A_BYTES + so, g_colh + go);
        }
        CP_COMMIT();
    };

    load_chunk(0, 0);
    load_chunk(1, 1);

    int st = 0;
    for (int kt = 0; kt < DCN_NCH; kt++) {
        if (kt + 2 < DCN_NCH) load_chunk((st + 2) % 3, kt + 2);
        else                  CP_COMMIT();
        CP_WAIT(2);
        __syncthreads();

        const uint32_t sA = sbase + st * STAGE_BYTES;
        const uint32_t sB = sA + A_BYTES;

#pragma unroll
        for (int ks = 0; ks < 2; ks++) {
            uint32_t ah[4][4], bf[4][2];

            const int arow = wm + (lane & 15);
            const int acol = ks * 16 + ((lane >> 4) << 3);
#pragma unroll
            for (int tm = 0; tm < 4; tm++) {
                uint32_t ao = (uint32_t)((arow + tm * 16) * A_STRIDE + acol) * 2;
                ldsm4(ah[tm], sA + ao);
            }
            const int bkrow = ks * 16 + (lane & 15);
#pragma unroll
            for (int ng = 0; ng < 2; ng++) {
                const int bcol = wn + ng * 16 + ((lane >> 4) << 3);
                uint32_t bo = (uint32_t)(bkrow * B_STRIDE + bcol) * 2;
                uint32_t t[4];
                ldsm4t(t, sB + bo);
                bf[2*ng][0] = t[0]; bf[2*ng][1] = t[1];
                bf[2*ng+1][0] = t[2]; bf[2*ng+1][1] = t[3];
            }
#pragma unroll
            for (int tm = 0; tm < 4; tm++)
#pragma unroll
                for (int tn = 0; tn < 4; tn++)
                    mma_fp(acc[tm][tn], ah[tm], bf[tn]);
        }
        __syncthreads();
        st = (st + 1) % 3;
    }

    const int rowl = lane >> 2;
    const int colp = (lane & 3) * 2;
#pragma unroll
    for (int tm = 0; tm < 4; tm++) {
#pragma unroll
        for (int half = 0; half < 2; half++) {
            const int m = m0 + wm + tm * 16 + rowl + half * 8;
            const float add = g_add2[m];
            const __half* pr = g_projh + ((size_t)bb * C + m) * HW + hw0 + wn + colp;
            float*        ob = out     + ((size_t)bb * C + m) * HW + hw0 + wn + colp;
#pragma unroll
            for (int tn = 0; tn < 4; tn++) {
                float2 p = __half22float2(*(const __half2*)(pr + tn * 8));
                float2 r;
                r.x = fmaxf(acc[tm][tn][half * 2 + 0] + add + p.x, 0.0f);
                r.y = fmaxf(acc[tm][tn][half * 2 + 1] + add + p.y, 0.0f);
                *(float2*)(ob + tn * 8) = r;
            }
        }
    }
}

// ---------------- launch ----------------------------------------------------
extern "C" void kernel_launch(void* const* d_in, const int* in_sizes, int n_in,
                              void* d_out, int out_size)
{
    const float* feature = (const float*)d_in[0];
    const float* p1_w    = (const float*)d_in[1];
    const float* p1_b    = (const float*)d_in[2];
    const float* bn1_g   = (const float*)d_in[3];
    const float* bn1_b   = (const float*)d_in[4];
    const float* bn1_m   = (const float*)d_in[5];
    const float* bn1_v   = (const float*)d_in[6];
    const float* off_w   = (const float*)d_in[7];
    const float* off_b   = (const float*)d_in[8];
    const float* dcn_w   = (const float*)d_in[9];
    const float* dcn_b   = (const float*)d_in[10];
    const float* bn2_g   = (const float*)d_in[11];
    const float* bn2_b   = (const float*)d_in[12];
    const float* bn2_m   = (const float*)d_in[13];
    const float* bn2_v   = (const float*)d_in[14];

    cudaFuncSetAttribute(dcn_gemm_kernel,
                         cudaFuncAttributeMaxDynamicSharedMemorySize, DCN_SMEM);
    cudaFuncSetAttribute(off_gemm_kernel,
                         cudaFuncAttributeMaxDynamicSharedMemorySize, OC_SMEM);
    cudaFuncSetAttribute(proj_tc_kernel,
                         cudaFuncAttributeMaxDynamicSharedMemorySize, PJ_SMEM);

    prep_small_kernel<<<PS_TOTAL, 256>>>(p1_w, p1_b, bn1_g, bn1_b, bn1_m, bn1_v,
                                         off_w, dcn_w, dcn_b,
                                         bn2_g, bn2_b, bn2_m, bn2_v);
    conv_f16_kernel<<<(int)((size_t)BATCH * CHW / 2048), 256>>>(feature);

    proj_tc_kernel<<<dim3(NPIX / 128, 2), 256, PJ_SMEM>>>();

    pack_kernel<<<dim3(2, 16, 512), 256>>>();

    off_gemm_kernel<<<NPIX / 256, 256, OC_SMEM>>>(off_b);

    sample_v2_kernel<<<dim3(H, KK, BATCH), 256>>>();

    dcn_gemm_kernel<<<dim3(NPIX / 128, C / 128), 256, DCN_SMEM>>>((float*)d_out);
}